// round 17
// baseline (speedup 1.0000x reference)
#include <cuda_runtime.h>
#include <cuda_bf16.h>
#include <cstdint>

// Problem constants (from reference)
#define B_  8
#define L_  2048
#define P_  576
#define V_  32000
#define D_  2560
#define T_  (L_ - 1 + P_)      // 2623
#define IGNORE_INDEX_ (-100)

// Write-through float4 store: output stream takes no L2 lines.
__device__ __forceinline__ void stwt4(float4* p, float4 v) {
    asm volatile("st.global.wt.v4.f32 [%0], {%1,%2,%3,%4};"
                 :: "l"(p), "f"(v.x), "f"(v.y), "f"(v.z), "f"(v.w)
                 : "memory");
}

// Probe: 64-thread blocks, one row per block -> 10 unconditional float4
// per thread, all loads front-batched (per-warp MLP = 10), finer CTA
// granularity for the work-stealing scheduler.
//
// Cache policy (champion settings, A/B-measured):
//   embed_table    -> __ldg  : reused working set, L2-cached
//   image_features -> __ldcs : read-once streaming, evict-first
//   output         -> st.wt  : write-through, zero L2 allocation
__global__ void __launch_bounds__(64)
splice_kernel64(const float* __restrict__ embed_table,     // [V, D]
                const float* __restrict__ image_features,  // [B, P, D]
                const int*   __restrict__ input_ids,       // [B, L]
                const int*   __restrict__ labels,          // [B, L]
                const int*   __restrict__ img_pos,         // [B]
                float* __restrict__ out)
{
    const int row = blockIdx.x;           // 0 .. B*T-1
    const int b = row / T_;
    const int t = row - b * T_;

    const int pos = img_pos[b];
    const bool is_img = (t >= pos) && (t < pos + P_);

    int tok_idx = (t < pos) ? t : (t - P_ + 1);
    tok_idx = max(0, min(tok_idx, L_ - 1));

    float4* __restrict__ dst =
        reinterpret_cast<float4*>(out + (long long)row * D_);

    const int tid = threadIdx.x;          // 0..63

    if (is_img) {
        const int img_idx = max(0, min(t - pos, P_ - 1));
        const float4* __restrict__ src = reinterpret_cast<const float4*>(
            image_features + ((long long)b * P_ + img_idx) * D_);
        float4 v0 = __ldcs(src + tid);
        float4 v1 = __ldcs(src + tid + 64);
        float4 v2 = __ldcs(src + tid + 128);
        float4 v3 = __ldcs(src + tid + 192);
        float4 v4 = __ldcs(src + tid + 256);
        float4 v5 = __ldcs(src + tid + 320);
        float4 v6 = __ldcs(src + tid + 384);
        float4 v7 = __ldcs(src + tid + 448);
        float4 v8 = __ldcs(src + tid + 512);
        float4 v9 = __ldcs(src + tid + 576);
        stwt4(dst + tid,       v0);
        stwt4(dst + tid + 64,  v1);
        stwt4(dst + tid + 128, v2);
        stwt4(dst + tid + 192, v3);
        stwt4(dst + tid + 256, v4);
        stwt4(dst + tid + 320, v5);
        stwt4(dst + tid + 384, v6);
        stwt4(dst + tid + 448, v7);
        stwt4(dst + tid + 512, v8);
        stwt4(dst + tid + 576, v9);
    } else {
        const int tok = input_ids[b * L_ + tok_idx];
        const float4* __restrict__ src = reinterpret_cast<const float4*>(
            embed_table + (long long)tok * D_);
        float4 v0 = __ldg(src + tid);
        float4 v1 = __ldg(src + tid + 64);
        float4 v2 = __ldg(src + tid + 128);
        float4 v3 = __ldg(src + tid + 192);
        float4 v4 = __ldg(src + tid + 256);
        float4 v5 = __ldg(src + tid + 320);
        float4 v6 = __ldg(src + tid + 384);
        float4 v7 = __ldg(src + tid + 448);
        float4 v8 = __ldg(src + tid + 512);
        float4 v9 = __ldg(src + tid + 576);
        stwt4(dst + tid,       v0);
        stwt4(dst + tid + 64,  v1);
        stwt4(dst + tid + 128, v2);
        stwt4(dst + tid + 192, v3);
        stwt4(dst + tid + 256, v4);
        stwt4(dst + tid + 320, v5);
        stwt4(dst + tid + 384, v6);
        stwt4(dst + tid + 448, v7);
        stwt4(dst + tid + 512, v8);
        stwt4(dst + tid + 576, v9);
    }

    if (tid == 0) {
        float* tails = out + (long long)B_ * T_ * D_;
        // new_labels
        tails[row] = is_img ? (float)IGNORE_INDEX_
                            : (float)labels[b * L_ + tok_idx];
        // attention_mask (all true)
        tails[(long long)B_ * T_ + row] = 1.0f;
        // position_ids (iota over T)
        tails[2LL * B_ * T_ + row] = (float)t;
    }
}

extern "C" void kernel_launch(void* const* d_in, const int* in_sizes, int n_in,
                              void* d_out, int out_size)
{
    const float* embed_table    = (const float*)d_in[0];
    const float* image_features = (const float*)d_in[1];
    const int*   input_ids      = (const int*)  d_in[2];
    const int*   labels         = (const int*)  d_in[3];
    const int*   img_pos        = (const int*)  d_in[4];
    float* out = (float*)d_out;

    const int n_rows = B_ * T_;   // 20984
    splice_kernel64<<<n_rows, 64>>>(embed_table, image_features,
                                    input_ids, labels, img_pos, out);
}